// round 13
// baseline (speedup 1.0000x reference)
#include <cuda_runtime.h>
#include <cuda_bf16.h>
#include <math.h>
#include <stdint.h>

#define BB 2
#define HH 8
#define NN 512
#define TT 512
#define MM 512
#define CC 2048

#define X_ELEMS   (BB*NN*512)
#define OUT_F2    (BB*HH*NN*64)

// ---------------- scratch ----------------
__device__ float g_kraw[BB*NN*512];
__device__ float g_v   [BB*NN*512];
__device__ float g_part[128];
__device__ float g_Ac[256*TT];
__device__ float g_As[256*TT];
__device__ float g_inb[TT*CC];
__device__ float g_re [MM*CC];
__device__ float g_im [MM*CC];

__device__ __forceinline__ float tf32r(float x) {
    uint32_t u;
    asm("cvt.rna.tf32.f32 %0, %1;" : "=r"(u) : "f"(x));
    return __uint_as_float(u);
}
__device__ __forceinline__ void mma_tf32(float d[4], const uint32_t a[4], const uint32_t b[2]) {
    asm volatile(
        "mma.sync.aligned.m16n8k8.row.col.f32.tf32.tf32.f32 "
        "{%0,%1,%2,%3}, {%4,%5,%6,%7}, {%8,%9}, {%0,%1,%2,%3};"
        : "+f"(d[0]), "+f"(d[1]), "+f"(d[2]), "+f"(d[3])
        : "r"(a[0]), "r"(a[1]), "r"(a[2]), "r"(a[3]), "r"(b[0]), "r"(b[1]));
}

// ---------------- K1: projections via mma.sync 3xTF32 ----------------
// grid (16, 8): bn 0..7 -> Wk cols bn*64; bn 8..15 -> Wv cols (bn-8)*64. bm -> rows bm*128.
// Block tile 128m x 64n, K=512 in 32 chunks of 16 (2 k8 mma steps each).
// 8 warps = 4m x 2n, warp tile 32x32. Row stride 20 floats -> all frag LDS conflict-free.
#define PSTRIDE 20
__global__ void k_proj_mma(const float* __restrict__ X,
                           const float* __restrict__ Wkm,
                           const float* __restrict__ Wvm) {
    __shared__ __align__(16) float sAh[128*PSTRIDE];
    __shared__ __align__(16) float sAl[128*PSTRIDE];
    __shared__ __align__(16) float sBh[64*PSTRIDE];
    __shared__ __align__(16) float sBl[64*PSTRIDE];
    __shared__ float sred[8];

    const int tid = threadIdx.x, wid = tid >> 5, lid = tid & 31;
    const int bn = blockIdx.x, bm = blockIdx.y;
    const int m0 = bm * 128;
    const bool isK = (bn < 8);
    const float* Wm = isK ? Wkm : Wvm;
    const int n0 = (bn & 7) * 64;

    const int g  = lid >> 2;         // 0..7
    const int tg = lid & 3;          // 0..3
    const int wm = (wid & 3) * 32;   // warp m offset
    const int wn = (wid >> 2) * 32;  // warp n offset

    float d[2][4][4] = {};           // [mt][nt][reg]

    for (int c = 0; c < 32; c++) {
        const int k0 = c * 16;
        // ---- X tile: 128 rows x 16 k (fp32 -> tf32 hi/lo) ----
#pragma unroll
        for (int it = 0; it < 2; it++) {
            int i = tid + it * 256;            // 0..511
            int r = i >> 2, kq = i & 3;
            float4 xv = *(const float4*)(X + (m0 + r) * 512 + k0 + kq * 4);
            float4 hi, lo;
            hi.x = tf32r(xv.x); lo.x = tf32r(xv.x - hi.x);
            hi.y = tf32r(xv.y); lo.y = tf32r(xv.y - hi.y);
            hi.z = tf32r(xv.z); lo.z = tf32r(xv.z - hi.z);
            hi.w = tf32r(xv.w); lo.w = tf32r(xv.w - hi.w);
            *(float4*)(sAh + r * PSTRIDE + kq * 4) = hi;
            *(float4*)(sAl + r * PSTRIDE + kq * 4) = lo;
        }
        // ---- W tile: 16 k x 64 n -> sB[n][k] (transpose + split) ----
        {
            int n = tid & 63, kq = tid >> 6;   // kq 0..3
#pragma unroll
            for (int j = 0; j < 4; j++) {
                int kk = kq * 4 + j;
                float wv = Wm[(size_t)(k0 + kk) * 512 + n0 + n];
                float hi = tf32r(wv);
                sBh[n * PSTRIDE + kk] = hi;
                sBl[n * PSTRIDE + kk] = tf32r(wv - hi);
            }
        }
        __syncthreads();

#pragma unroll
        for (int ksub = 0; ksub < 2; ksub++) {
            const int ko = ksub * 8;
            uint32_t ah[2][4], al[2][4], bh[4][2], bl[4][2];
#pragma unroll
            for (int mt = 0; mt < 2; mt++) {
                int rb  = (wm + mt * 16 + g) * PSTRIDE + ko;
                int rb8 = rb + 8 * PSTRIDE;
                ah[mt][0] = __float_as_uint(sAh[rb + tg]);
                ah[mt][1] = __float_as_uint(sAh[rb8 + tg]);
                ah[mt][2] = __float_as_uint(sAh[rb + tg + 4]);
                ah[mt][3] = __float_as_uint(sAh[rb8 + tg + 4]);
                al[mt][0] = __float_as_uint(sAl[rb + tg]);
                al[mt][1] = __float_as_uint(sAl[rb8 + tg]);
                al[mt][2] = __float_as_uint(sAl[rb + tg + 4]);
                al[mt][3] = __float_as_uint(sAl[rb8 + tg + 4]);
            }
#pragma unroll
            for (int nt = 0; nt < 4; nt++) {
                int nb = (wn + nt * 8 + g) * PSTRIDE + ko;
                bh[nt][0] = __float_as_uint(sBh[nb + tg]);
                bh[nt][1] = __float_as_uint(sBh[nb + tg + 4]);
                bl[nt][0] = __float_as_uint(sBl[nb + tg]);
                bl[nt][1] = __float_as_uint(sBl[nb + tg + 4]);
            }
#pragma unroll
            for (int mt = 0; mt < 2; mt++)
#pragma unroll
                for (int nt = 0; nt < 4; nt++) {
                    mma_tf32(d[mt][nt], ah[mt], bh[nt]);
                    mma_tf32(d[mt][nt], ah[mt], bl[nt]);
                    mma_tf32(d[mt][nt], al[mt], bh[nt]);
                }
        }
        __syncthreads();
    }

    // ---- epilogue: store D + norm partial ----
    float* outp = isK ? g_kraw : g_v;
    float nsum = 0.f;
#pragma unroll
    for (int mt = 0; mt < 2; mt++)
#pragma unroll
        for (int nt = 0; nt < 4; nt++) {
            int mr = m0 + wm + mt * 16 + g;
            int nc = n0 + wn + nt * 8 + tg * 2;
            *(float2*)(outp + (size_t)mr * 512 + nc)       = make_float2(d[mt][nt][0], d[mt][nt][1]);
            *(float2*)(outp + (size_t)(mr + 8) * 512 + nc) = make_float2(d[mt][nt][2], d[mt][nt][3]);
            nsum += d[mt][nt][0]*d[mt][nt][0] + d[mt][nt][1]*d[mt][nt][1]
                  + d[mt][nt][2]*d[mt][nt][2] + d[mt][nt][3]*d[mt][nt][3];
        }
#pragma unroll
    for (int o = 16; o > 0; o >>= 1) nsum += __shfl_down_sync(0xffffffffu, nsum, o);
    if (lid == 0) sred[wid] = nsum;
    __syncthreads();
    if (tid == 0) {
        float s = 0.f;
#pragma unroll
        for (int w = 0; w < 8; w++) s += sred[w];
        g_part[bm * 16 + bn] = isK ? s : 0.f;
    }
}

// ---------------- K3: rnorm + elu + per-head sums + pack B + build DFT table ----------
__global__ void k_prep() {
    int bt = blockIdx.x;           // b*512 + t
    int b  = bt >> 9;
    int t  = bt & 511;
    int tid = threadIdx.x;         // 0..511 = h*64 + j

    __shared__ float rs[128];
    __shared__ float sh_rn;
    if (tid < 128) rs[tid] = g_part[tid];
    if (bt < 256) {
        int k = (bt * tid) & 1023;
        float sn, cn;
        sincospif((float)k * (1.0f / 512.0f), &sn, &cn);
        g_Ac[bt*TT + tid] = cn;
        g_As[bt*TT + tid] = -sn;
    }
    __syncthreads();
    if (tid < 64) rs[tid] += rs[tid + 64];
    __syncthreads();
    if (tid < 32) {
        float v = rs[tid] + rs[tid + 32];
#pragma unroll
        for (int o = 16; o > 0; o >>= 1) v += __shfl_down_sync(0xffffffffu, v, o);
        if (tid == 0) sh_rn = rsqrtf(v);
    }
    __syncthreads();
    float rn = sh_rn;

    float kv = g_kraw[bt*512 + tid] * rn;
    float ke = kv > 0.f ? kv : expm1f(kv);

    float s = ke;
#pragma unroll
    for (int o = 16; o > 0; o >>= 1) s += __shfl_down_sync(0xffffffffu, s, o);
    __shared__ float wsum[16];
    __shared__ float hsum[8];
    int warp = tid >> 5;
    if ((tid & 31) == 0) wsum[warp] = s;
    __syncthreads();
    if (tid < 8) hsum[tid] = wsum[2*tid] + wsum[2*tid + 1];
    __syncthreads();

    int h = tid >> 6;
    float u = hsum[h] * g_v[bt*512 + tid];
    g_inb[t*CC + b*512 + tid]        = u;
    g_inb[t*CC + 1024 + b*512 + tid] = ke;
}

// ---------------- K4: octo-row DFT GEMM, single wave (base rows 1..64) ----------------
__global__ void k_dft() {
    const int tidx = threadIdx.x;
    const int tx = tidx & 15;
    const int ty = tidx >> 4;
    const int n0 = blockIdx.x * 64;
    const int m0 = blockIdx.y * 16 + 1;

    __shared__ float sAc[16][17];
    __shared__ float sAn[16][17];
    __shared__ float sB [16][64];

    float C [8][4] = {};
    float Nn[8][4] = {};
    float P [8][4] = {};
    const bool doP = (blockIdx.y == 0) && (ty < 2);

    for (int k0 = 0; k0 < 512; k0 += 16) {
        {
            int t = tidx & 15, row = tidx >> 4;
            int idx = (m0 + row)*TT + k0 + t;
            sAc[t][row] = g_Ac[idx];
            sAn[t][row] = g_As[idx];
        }
        {
            int c = tidx & 63, tb = tidx >> 6;
#pragma unroll
            for (int i = 0; i < 4; i++)
                sB[tb + i*4][c] = g_inb[(k0 + tb + i*4)*CC + n0 + c];
        }
        __syncthreads();
#pragma unroll
        for (int kk = 0; kk < 16; kk++) {
            const int p = kk & 7;
            float c = sAc[kk][ty];
            float s = sAn[kk][ty];
            float4 b4 = *(const float4*)&sB[kk][tx*4];
            C [p][0] += c*b4.x; C [p][1] += c*b4.y; C [p][2] += c*b4.z; C [p][3] += c*b4.w;
            Nn[p][0] += s*b4.x; Nn[p][1] += s*b4.y; Nn[p][2] += s*b4.z; Nn[p][3] += s*b4.w;
            if (doP) {
                P[p][0] += b4.x; P[p][1] += b4.y; P[p][2] += b4.z; P[p][3] += b4.w;
            }
        }
        __syncthreads();
    }

    const int mp = m0 + ty;
    const float R = 0.70710678118654752f;
#pragma unroll
    for (int cc = 0; cc < 4; cc++) {
        int col = n0 + tx*4 + cc;
        float C0=C[0][cc],C1=C[1][cc],C2=C[2][cc],C3=C[3][cc];
        float C4=C[4][cc],C5=C[5][cc],C6=C[6][cc],C7=C[7][cc];
        float S0=-Nn[0][cc],S1=-Nn[1][cc],S2=-Nn[2][cc],S3=-Nn[3][cc];
        float S4=-Nn[4][cc],S5=-Nn[5][cc],S6=-Nn[6][cc],S7=-Nn[7][cc];
        float T0c=C0+C4,T1c=C1+C5,T2c=C2+C6,T3c=C3+C7;
        float T0s=S0+S4,T1s=S1+S5,T2s=S2+S6,T3s=S3+S7;
        float U0c=C0-C4,U1c=C1-C5,U2c=C2-C6,U3c=C3-C7;
        float U0s=S0-S4,U1s=S1-S5,U2s=S2-S6,U3s=S3-S7;

        {
            int o = mp*CC + col;
            g_re[o] = T0c+T1c+T2c+T3c;
            g_im[o] = -(T0s+T1s+T2s+T3s);
        }
        {
            int o = (512-mp)*CC + col;
            g_re[o] = T0c-T1c+T2c-T3c;
            g_im[o] = T0s-T1s+T2s-T3s;
        }
        if (mp <= 63) {
            int o = (256-mp)*CC + col;
            g_re[o] = (T0c-T2c) + (T1s-T3s);
            g_im[o] = (T0s-T2s) - (T1c-T3c);
        }
        {
            int o = (256+mp)*CC + col;
            g_re[o] = (T0c-T2c) - (T1s-T3s);
            g_im[o] = -((T0s-T2s) + (T1c-T3c));
        }
        if (mp <= 63) {
            int o = (128-mp)*CC + col;
            g_re[o] = U0c + U2s + R*((U1c+U1s) + (U3s-U3c));
            g_im[o] = -(-U0s + U2c + R*((U1c-U1s) + (U3c+U3s)));
        }
        {
            int o = (128+mp)*CC + col;
            g_re[o] = U0c - U2s + R*((U1c-U1s) - (U3c+U3s));
            g_im[o] = -(U0s + U2c + R*((U1c+U1s) + (U3c-U3s)));
        }
        if (mp <= 63) {
            int o = (384-mp)*CC + col;
            g_re[o] = U0c - U2s + R*((U1s-U1c) + (U3c+U3s));
            g_im[o] = -(-U0s - U2c + R*((U1c+U1s) + (U3c-U3s)));
        }
        if (mp <= 63) {
            int o = (384+mp)*CC + col;
            g_re[o] = U0c + U2s - R*(U1c+U1s) + R*(U3c-U3s);
            g_im[o] = -(U0s - U2c + R*((U1c-U1s) + (U3c+U3s)));
        }

        if (blockIdx.y == 0 && ty == 0) {
            float P0=P[0][cc],P1=P[1][cc],P2=P[2][cc],P3=P[3][cc];
            float P4=P[4][cc],P5=P[5][cc],P6=P[6][cc],P7=P[7][cc];
            float A  = P0 - P4;
            float Bq = P1 - P3 - P5 + P7;
            float Cq = P2 - P6;
            float Dq = P1 + P3 - P5 - P7;
            g_re[col]          = P0+P1+P2+P3+P4+P5+P6+P7;
            g_im[col]          = 0.f;
            g_re[128*CC + col] = A + R*Bq;
            g_im[128*CC + col] = -(Cq + R*Dq);
            g_re[256*CC + col] = P0 - P2 + P4 - P6;
            g_im[256*CC + col] = -(P1 - P3 + P5 - P7);
            g_re[384*CC + col] = A - R*Bq;
            g_im[384*CC + col] = -(-Cq + R*Dq);
        }
    }
}

// ---------------- K5: (b,h) 2x8 DFT mix + complex division (256-thread blocks) --------
__global__ void k_mix(float* __restrict__ out, int cap_floats, int mode) {
    int m = blockIdx.x * 4 + (threadIdx.x >> 6);   // 0..511
    int j = threadIdx.x & 63;                      // 0..63

    float pur[16], pui[16], pkr[16], pki[16];
#pragma unroll
    for (int bh = 0; bh < 16; bh++) {
        int cu = m*CC + bh*64 + j;
        pur[bh] = g_re[cu];        pui[bh] = g_im[cu];
        pkr[bh] = g_re[cu + 1024]; pki[bh] = g_im[cu + 1024];
    }

    const float R2 = 0.70710678118654752f;
    const float w8r[8] = {1.f,  R2, 0.f, -R2, -1.f, -R2, 0.f,  R2};
    const float w8i[8] = {0.f, -R2, -1.f, -R2, 0.f,  R2, 1.f,  R2};

#pragma unroll
    for (int h0 = 0; h0 < 8; h0++) {
        float eur=0,eui=0,our_=0,oui=0, ekr=0,eki=0,okr=0,oki=0;
#pragma unroll
        for (int hp = 0; hp < 8; hp++) {
            int kq = (h0 * hp) & 7;
            float wr = w8r[kq], wi = w8i[kq];
            eur  += wr*pur[hp]   - wi*pui[hp];
            eui  += wr*pui[hp]   + wi*pur[hp];
            our_ += wr*pur[8+hp] - wi*pui[8+hp];
            oui  += wr*pui[8+hp] + wi*pur[8+hp];
            ekr  += wr*pkr[hp]   - wi*pki[hp];
            eki  += wr*pki[hp]   + wi*pkr[hp];
            okr  += wr*pkr[8+hp] - wi*pki[8+hp];
            oki  += wr*pki[8+hp] + wi*pkr[8+hp];
        }
#pragma unroll
        for (int b0 = 0; b0 < 2; b0++) {
            float sg = b0 ? -1.f : 1.f;
            float nr = eur + sg*our_, ni = eui + sg*oui;
            float dr = ekr + sg*okr,  di = eki + sg*oki;
            float inv = 1.0f / (dr*dr + di*di);
            float orr = (nr*dr + ni*di) * inv;
            float oii = (ni*dr - nr*di) * inv;
            int idx = (((b0*8 + h0)*512 + m)*64) + j;
            if (mode) {
                int f = 2*idx;
                if (f + 1 < cap_floats) { out[f] = orr; out[f+1] = oii; }
            } else {
                if (idx < cap_floats) out[idx] = orr;
            }
        }
    }
}

// ---------------- launch ----------------
extern "C" void kernel_launch(void* const* d_in, const int* in_sizes, int n_in,
                              void* d_out, int out_size) {
    const float* x = nullptr;
    const float* Ws[3] = {nullptr, nullptr, nullptr};

    int xi = -1; long long xmax = -1;
    for (int i = 0; i < n_in; i++)
        if ((long long)in_sizes[i] > xmax) { xmax = in_sizes[i]; xi = i; }
    if (xi >= 0) x = (const float*)d_in[xi];

    int wcount = 0;
    for (int i = 0; i < n_in && wcount < 3; i++) {
        if (i == xi) continue;
        int same = 0;
        for (int k2 = 0; k2 < n_in; k2++)
            if (k2 != xi && in_sizes[k2] == in_sizes[i]) same++;
        if (same == 3) Ws[wcount++] = (const float*)d_in[i];
    }
    if ((!Ws[0] || !Ws[1] || !Ws[2]) && n_in >= 4) {
        x = (const float*)d_in[0];
        Ws[0] = (const float*)d_in[1];
        Ws[1] = (const float*)d_in[2];
        Ws[2] = (const float*)d_in[3];
    }
    const float* Wk = Ws[1];
    const float* Wv = Ws[2];
    if (!x || !Wk || !Wv || !d_out || out_size <= 0) return;

    int mode, cap_floats;
    if (out_size >= 2*OUT_F2) { mode = 1; cap_floats = 2*OUT_F2; }
    else                      { mode = 0; cap_floats = out_size < OUT_F2 ? out_size : OUT_F2; }

    k_proj_mma<<<dim3(16, 8), 256>>>(x, Wk, Wv);
    k_prep<<<1024, 512>>>();
    k_dft<<<dim3(32, 4), 256>>>();
    k_mix<<<128, 256>>>((float*)d_out, cap_floats, mode);
}

// round 14
// speedup vs baseline: 1.1505x; 1.1505x over previous
#include <cuda_runtime.h>
#include <cuda_fp16.h>
#include <math.h>
#include <stdint.h>

#define BB 2
#define HH 8
#define NN 512
#define TT 512
#define MM 512
#define CC 2048

#define X_ELEMS   (BB*NN*512)
#define OUT_F2    (BB*HH*NN*64)

// ---------------- scratch ----------------
__device__ float g_kraw[BB*NN*512];
__device__ float g_v   [BB*NN*512];
__device__ float g_part[128];
__device__ float g_Ac[256*TT];
__device__ float g_As[256*TT];
__device__ float g_inb[TT*CC];
__device__ float g_re [MM*CC];
__device__ float g_im [MM*CC];

__device__ __forceinline__ uint32_t pack_h2(__half a, __half b) {
    __half2 t(a, b);
    return *reinterpret_cast<uint32_t*>(&t);
}
__device__ __forceinline__ void split4(float4 v, uint2& hi, uint2& lo) {
    __half h0 = __float2half(v.x), h1 = __float2half(v.y);
    __half h2 = __float2half(v.z), h3 = __float2half(v.w);
    __half l0 = __float2half(v.x - __half2float(h0));
    __half l1 = __float2half(v.y - __half2float(h1));
    __half l2 = __float2half(v.z - __half2float(h2));
    __half l3 = __float2half(v.w - __half2float(h3));
    hi.x = pack_h2(h0, h1); hi.y = pack_h2(h2, h3);
    lo.x = pack_h2(l0, l1); lo.y = pack_h2(l2, l3);
}
__device__ __forceinline__ void split1(float v, uint16_t& hi, uint16_t& lo) {
    __half h = __float2half(v);
    __half l = __float2half(v - __half2float(h));
    hi = *reinterpret_cast<uint16_t*>(&h);
    lo = *reinterpret_cast<uint16_t*>(&l);
}
__device__ __forceinline__ void mma_f16(float d[4], const uint32_t a[4], const uint32_t b[2]) {
    asm volatile(
        "mma.sync.aligned.m16n8k16.row.col.f32.f16.f16.f32 "
        "{%0,%1,%2,%3}, {%4,%5,%6,%7}, {%8,%9}, {%0,%1,%2,%3};"
        : "+f"(d[0]), "+f"(d[1]), "+f"(d[2]), "+f"(d[3])
        : "r"(a[0]), "r"(a[1]), "r"(a[2]), "r"(a[3]), "r"(b[0]), "r"(b[1]));
}

// ---------------- K1: projections via mma.sync fp16x3 ----------------
// grid (16, 8): bn 0..7 -> Wk cols bn*64; bn 8..15 -> Wv cols (bn-8)*64. bm -> rows bm*128.
// Block tile 128m x 64n, K=512 in 32 chunks of 16. 8 warps = 4m x 2n, warp tile 32x32.
#define ASTRIDE 48   // bytes per 16-k fp16 row (32B data + 16B pad) -> conflict-free frags
__global__ void k_proj_mma(const float* __restrict__ X,
                           const float* __restrict__ Wkm,
                           const float* __restrict__ Wvm) {
    __shared__ __align__(16) char sAh[128*ASTRIDE];
    __shared__ __align__(16) char sAl[128*ASTRIDE];
    __shared__ __align__(16) char sBh[64*ASTRIDE];
    __shared__ __align__(16) char sBl[64*ASTRIDE];
    __shared__ float sred[8];

    const int tid = threadIdx.x, wid = tid >> 5, lid = tid & 31;
    const int bn = blockIdx.x, bm = blockIdx.y;
    const int m0 = bm * 128;
    const bool isK = (bn < 8);
    const float* Wm = isK ? Wkm : Wvm;
    const int n0 = (bn & 7) * 64;

    const int g  = lid >> 2;         // 0..7
    const int tg = lid & 3;          // 0..3
    const int wm = (wid & 3) * 32;   // warp m offset
    const int wn = (wid >> 2) * 32;  // warp n offset

    float d[2][4][4] = {};           // [mt][nt][reg]

    for (int c = 0; c < 32; c++) {
        const int k0 = c * 16;
        // ---- X tile: 128 rows x 16 k (fp32 -> fp16 hi/lo) ----
#pragma unroll
        for (int it = 0; it < 2; it++) {
            int i = tid + it * 256;            // 0..511
            int r = i >> 2, kq = i & 3;
            float4 xv = *(const float4*)(X + (m0 + r) * 512 + k0 + kq * 4);
            uint2 hi, lo; split4(xv, hi, lo);
            *(uint2*)(sAh + r * ASTRIDE + kq * 8) = hi;
            *(uint2*)(sAl + r * ASTRIDE + kq * 8) = lo;
        }
        // ---- W tile: 16 k x 64 n -> sB[n][k] (transpose + split) ----
        {
            int n = tid & 63, kq = tid >> 6;   // kq 0..3
#pragma unroll
            for (int j = 0; j < 4; j++) {
                int kk = kq * 4 + j;
                float wv = Wm[(size_t)(k0 + kk) * 512 + n0 + n];
                uint16_t hi, lo; split1(wv, hi, lo);
                *(uint16_t*)(sBh + n * ASTRIDE + kk * 2) = hi;
                *(uint16_t*)(sBl + n * ASTRIDE + kk * 2) = lo;
            }
        }
        __syncthreads();

        // ---- fragment loads ----
        uint32_t ah[2][4], al[2][4], bh[4][2], bl[4][2];
#pragma unroll
        for (int mt = 0; mt < 2; mt++) {
            int r0 = (wm + mt * 16 + g) * ASTRIDE;
            int r1 = (wm + mt * 16 + g + 8) * ASTRIDE;
            ah[mt][0] = *(uint32_t*)(sAh + r0 + tg * 4);
            ah[mt][1] = *(uint32_t*)(sAh + r1 + tg * 4);
            ah[mt][2] = *(uint32_t*)(sAh + r0 + 16 + tg * 4);
            ah[mt][3] = *(uint32_t*)(sAh + r1 + 16 + tg * 4);
            al[mt][0] = *(uint32_t*)(sAl + r0 + tg * 4);
            al[mt][1] = *(uint32_t*)(sAl + r1 + tg * 4);
            al[mt][2] = *(uint32_t*)(sAl + r0 + 16 + tg * 4);
            al[mt][3] = *(uint32_t*)(sAl + r1 + 16 + tg * 4);
        }
#pragma unroll
        for (int nt = 0; nt < 4; nt++) {
            int rn = (wn + nt * 8 + g) * ASTRIDE;
            bh[nt][0] = *(uint32_t*)(sBh + rn + tg * 4);
            bh[nt][1] = *(uint32_t*)(sBh + rn + 16 + tg * 4);
            bl[nt][0] = *(uint32_t*)(sBl + rn + tg * 4);
            bl[nt][1] = *(uint32_t*)(sBl + rn + 16 + tg * 4);
        }
        __syncthreads();

        // ---- 3-term mma ----
#pragma unroll
        for (int mt = 0; mt < 2; mt++)
#pragma unroll
            for (int nt = 0; nt < 4; nt++) {
                mma_f16(d[mt][nt], ah[mt], bh[nt]);
                mma_f16(d[mt][nt], ah[mt], bl[nt]);
                mma_f16(d[mt][nt], al[mt], bh[nt]);
            }
    }

    // ---- epilogue: store D + norm partial ----
    float* outp = isK ? g_kraw : g_v;
    float nsum = 0.f;
#pragma unroll
    for (int mt = 0; mt < 2; mt++)
#pragma unroll
        for (int nt = 0; nt < 4; nt++) {
            int mr = m0 + wm + mt * 16 + g;
            int nc = n0 + wn + nt * 8 + tg * 2;
            *(float2*)(outp + (size_t)mr * 512 + nc)       = make_float2(d[mt][nt][0], d[mt][nt][1]);
            *(float2*)(outp + (size_t)(mr + 8) * 512 + nc) = make_float2(d[mt][nt][2], d[mt][nt][3]);
            nsum += d[mt][nt][0]*d[mt][nt][0] + d[mt][nt][1]*d[mt][nt][1]
                  + d[mt][nt][2]*d[mt][nt][2] + d[mt][nt][3]*d[mt][nt][3];
        }
#pragma unroll
    for (int o = 16; o > 0; o >>= 1) nsum += __shfl_down_sync(0xffffffffu, nsum, o);
    if (lid == 0) sred[wid] = nsum;
    __syncthreads();
    if (tid == 0) {
        float s = 0.f;
#pragma unroll
        for (int w = 0; w < 8; w++) s += sred[w];
        g_part[bm * 16 + bn] = isK ? s : 0.f;
    }
}

// ---------------- K3: rnorm + elu + per-head sums + pack B + build DFT table ----------
__global__ void k_prep() {
    int bt = blockIdx.x;           // b*512 + t
    int b  = bt >> 9;
    int t  = bt & 511;
    int tid = threadIdx.x;         // 0..511 = h*64 + j

    __shared__ float rs[128];
    __shared__ float sh_rn;
    if (tid < 128) rs[tid] = g_part[tid];
    if (bt < 256) {
        int k = (bt * tid) & 1023;
        float sn, cn;
        sincospif((float)k * (1.0f / 512.0f), &sn, &cn);
        g_Ac[bt*TT + tid] = cn;
        g_As[bt*TT + tid] = -sn;
    }
    __syncthreads();
    if (tid < 64) rs[tid] += rs[tid + 64];
    __syncthreads();
    if (tid < 32) {
        float v = rs[tid] + rs[tid + 32];
#pragma unroll
        for (int o = 16; o > 0; o >>= 1) v += __shfl_down_sync(0xffffffffu, v, o);
        if (tid == 0) sh_rn = rsqrtf(v);
    }
    __syncthreads();
    float rn = sh_rn;

    float kv = g_kraw[bt*512 + tid] * rn;
    float ke = kv > 0.f ? kv : expm1f(kv);

    float s = ke;
#pragma unroll
    for (int o = 16; o > 0; o >>= 1) s += __shfl_down_sync(0xffffffffu, s, o);
    __shared__ float wsum[16];
    __shared__ float hsum[8];
    int warp = tid >> 5;
    if ((tid & 31) == 0) wsum[warp] = s;
    __syncthreads();
    if (tid < 8) hsum[tid] = wsum[2*tid] + wsum[2*tid + 1];
    __syncthreads();

    int h = tid >> 6;
    float u = hsum[h] * g_v[bt*512 + tid];
    g_inb[t*CC + b*512 + tid]        = u;
    g_inb[t*CC + 1024 + b*512 + tid] = ke;
}

// ---------------- K4: octo-row DFT GEMM, single wave (base rows 1..64) ----------------
__global__ void k_dft() {
    const int tidx = threadIdx.x;
    const int tx = tidx & 15;
    const int ty = tidx >> 4;
    const int n0 = blockIdx.x * 64;
    const int m0 = blockIdx.y * 16 + 1;

    __shared__ float sAc[16][17];
    __shared__ float sAn[16][17];
    __shared__ float sB [16][64];

    float C [8][4] = {};
    float Nn[8][4] = {};
    float P [8][4] = {};
    const bool doP = (blockIdx.y == 0) && (ty < 2);

    for (int k0 = 0; k0 < 512; k0 += 16) {
        {
            int t = tidx & 15, row = tidx >> 4;
            int idx = (m0 + row)*TT + k0 + t;
            sAc[t][row] = g_Ac[idx];
            sAn[t][row] = g_As[idx];
        }
        {
            int c = tidx & 63, tb = tidx >> 6;
#pragma unroll
            for (int i = 0; i < 4; i++)
                sB[tb + i*4][c] = g_inb[(k0 + tb + i*4)*CC + n0 + c];
        }
        __syncthreads();
#pragma unroll
        for (int kk = 0; kk < 16; kk++) {
            const int p = kk & 7;
            float c = sAc[kk][ty];
            float s = sAn[kk][ty];
            float4 b4 = *(const float4*)&sB[kk][tx*4];
            C [p][0] += c*b4.x; C [p][1] += c*b4.y; C [p][2] += c*b4.z; C [p][3] += c*b4.w;
            Nn[p][0] += s*b4.x; Nn[p][1] += s*b4.y; Nn[p][2] += s*b4.z; Nn[p][3] += s*b4.w;
            if (doP) {
                P[p][0] += b4.x; P[p][1] += b4.y; P[p][2] += b4.z; P[p][3] += b4.w;
            }
        }
        __syncthreads();
    }

    const int mp = m0 + ty;
    const float R = 0.70710678118654752f;
#pragma unroll
    for (int cc = 0; cc < 4; cc++) {
        int col = n0 + tx*4 + cc;
        float C0=C[0][cc],C1=C[1][cc],C2=C[2][cc],C3=C[3][cc];
        float C4=C[4][cc],C5=C[5][cc],C6=C[6][cc],C7=C[7][cc];
        float S0=-Nn[0][cc],S1=-Nn[1][cc],S2=-Nn[2][cc],S3=-Nn[3][cc];
        float S4=-Nn[4][cc],S5=-Nn[5][cc],S6=-Nn[6][cc],S7=-Nn[7][cc];
        float T0c=C0+C4,T1c=C1+C5,T2c=C2+C6,T3c=C3+C7;
        float T0s=S0+S4,T1s=S1+S5,T2s=S2+S6,T3s=S3+S7;
        float U0c=C0-C4,U1c=C1-C5,U2c=C2-C6,U3c=C3-C7;
        float U0s=S0-S4,U1s=S1-S5,U2s=S2-S6,U3s=S3-S7;

        {
            int o = mp*CC + col;
            g_re[o] = T0c+T1c+T2c+T3c;
            g_im[o] = -(T0s+T1s+T2s+T3s);
        }
        {
            int o = (512-mp)*CC + col;
            g_re[o] = T0c-T1c+T2c-T3c;
            g_im[o] = T0s-T1s+T2s-T3s;
        }
        if (mp <= 63) {
            int o = (256-mp)*CC + col;
            g_re[o] = (T0c-T2c) + (T1s-T3s);
            g_im[o] = (T0s-T2s) - (T1c-T3c);
        }
        {
            int o = (256+mp)*CC + col;
            g_re[o] = (T0c-T2c) - (T1s-T3s);
            g_im[o] = -((T0s-T2s) + (T1c-T3c));
        }
        if (mp <= 63) {
            int o = (128-mp)*CC + col;
            g_re[o] = U0c + U2s + R*((U1c+U1s) + (U3s-U3c));
            g_im[o] = -(-U0s + U2c + R*((U1c-U1s) + (U3c+U3s)));
        }
        {
            int o = (128+mp)*CC + col;
            g_re[o] = U0c - U2s + R*((U1c-U1s) - (U3c+U3s));
            g_im[o] = -(U0s + U2c + R*((U1c+U1s) + (U3c-U3s)));
        }
        if (mp <= 63) {
            int o = (384-mp)*CC + col;
            g_re[o] = U0c - U2s + R*((U1s-U1c) + (U3c+U3s));
            g_im[o] = -(-U0s - U2c + R*((U1c+U1s) + (U3c-U3s)));
        }
        if (mp <= 63) {
            int o = (384+mp)*CC + col;
            g_re[o] = U0c + U2s - R*(U1c+U1s) + R*(U3c-U3s);
            g_im[o] = -(U0s - U2c + R*((U1c-U1s) + (U3c+U3s)));
        }

        if (blockIdx.y == 0 && ty == 0) {
            float P0=P[0][cc],P1=P[1][cc],P2=P[2][cc],P3=P[3][cc];
            float P4=P[4][cc],P5=P[5][cc],P6=P[6][cc],P7=P[7][cc];
            float A  = P0 - P4;
            float Bq = P1 - P3 - P5 + P7;
            float Cq = P2 - P6;
            float Dq = P1 + P3 - P5 - P7;
            g_re[col]          = P0+P1+P2+P3+P4+P5+P6+P7;
            g_im[col]          = 0.f;
            g_re[128*CC + col] = A + R*Bq;
            g_im[128*CC + col] = -(Cq + R*Dq);
            g_re[256*CC + col] = P0 - P2 + P4 - P6;
            g_im[256*CC + col] = -(P1 - P3 + P5 - P7);
            g_re[384*CC + col] = A - R*Bq;
            g_im[384*CC + col] = -(-Cq + R*Dq);
        }
    }
}

// ---------------- K5: (b,h) 2x8 DFT mix + complex division ----------------
__global__ void k_mix(float* __restrict__ out, int cap_floats, int mode) {
    int m = blockIdx.x;
    int j = threadIdx.x;

    float pur[16], pui[16], pkr[16], pki[16];
#pragma unroll
    for (int bh = 0; bh < 16; bh++) {
        int cu = m*CC + bh*64 + j;
        pur[bh] = g_re[cu];        pui[bh] = g_im[cu];
        pkr[bh] = g_re[cu + 1024]; pki[bh] = g_im[cu + 1024];
    }

    const float R2 = 0.70710678118654752f;
    const float w8r[8] = {1.f,  R2, 0.f, -R2, -1.f, -R2, 0.f,  R2};
    const float w8i[8] = {0.f, -R2, -1.f, -R2, 0.f,  R2, 1.f,  R2};

#pragma unroll
    for (int h0 = 0; h0 < 8; h0++) {
        float eur=0,eui=0,our_=0,oui=0, ekr=0,eki=0,okr=0,oki=0;
#pragma unroll
        for (int hp = 0; hp < 8; hp++) {
            int kq = (h0 * hp) & 7;
            float wr = w8r[kq], wi = w8i[kq];
            eur  += wr*pur[hp]   - wi*pui[hp];
            eui  += wr*pui[hp]   + wi*pur[hp];
            our_ += wr*pur[8+hp] - wi*pui[8+hp];
            oui  += wr*pui[8+hp] + wi*pur[8+hp];
            ekr  += wr*pkr[hp]   - wi*pki[hp];
            eki  += wr*pki[hp]   + wi*pkr[hp];
            okr  += wr*pkr[8+hp] - wi*pki[8+hp];
            oki  += wr*pki[8+hp] + wi*pkr[8+hp];
        }
#pragma unroll
        for (int b0 = 0; b0 < 2; b0++) {
            float sg = b0 ? -1.f : 1.f;
            float nr = eur + sg*our_, ni = eui + sg*oui;
            float dr = ekr + sg*okr,  di = eki + sg*oki;
            float inv = 1.0f / (dr*dr + di*di);
            float orr = (nr*dr + ni*di) * inv;
            float oii = (ni*dr - nr*di) * inv;
            int idx = (((b0*8 + h0)*512 + m)*64) + j;
            if (mode) {
                int f = 2*idx;
                if (f + 1 < cap_floats) { out[f] = orr; out[f+1] = oii; }
            } else {
                if (idx < cap_floats) out[idx] = orr;
            }
        }
    }
}

// ---------------- launch ----------------
extern "C" void kernel_launch(void* const* d_in, const int* in_sizes, int n_in,
                              void* d_out, int out_size) {
    const float* x = nullptr;
    const float* Ws[3] = {nullptr, nullptr, nullptr};

    int xi = -1; long long xmax = -1;
    for (int i = 0; i < n_in; i++)
        if ((long long)in_sizes[i] > xmax) { xmax = in_sizes[i]; xi = i; }
    if (xi >= 0) x = (const float*)d_in[xi];

    int wcount = 0;
    for (int i = 0; i < n_in && wcount < 3; i++) {
        if (i == xi) continue;
        int same = 0;
        for (int k2 = 0; k2 < n_in; k2++)
            if (k2 != xi && in_sizes[k2] == in_sizes[i]) same++;
        if (same == 3) Ws[wcount++] = (const float*)d_in[i];
    }
    if ((!Ws[0] || !Ws[1] || !Ws[2]) && n_in >= 4) {
        x = (const float*)d_in[0];
        Ws[0] = (const float*)d_in[1];
        Ws[1] = (const float*)d_in[2];
        Ws[2] = (const float*)d_in[3];
    }
    const float* Wk = Ws[1];
    const float* Wv = Ws[2];
    if (!x || !Wk || !Wv || !d_out || out_size <= 0) return;

    int mode, cap_floats;
    if (out_size >= 2*OUT_F2) { mode = 1; cap_floats = 2*OUT_F2; }
    else                      { mode = 0; cap_floats = out_size < OUT_F2 ? out_size : OUT_F2; }

    k_proj_mma<<<dim3(16, 8), 256>>>(x, Wk, Wv);
    k_prep<<<1024, 512>>>();
    k_dft<<<dim3(32, 4), 256>>>();
    k_mix<<<512, 64>>>((float*)d_out, cap_floats, mode);
}